// round 16
// baseline (speedup 1.0000x reference)
#include <cuda_runtime.h>
#include <cstdint>

#define N_FEAT 512
#define N_HID  16
#define N_CLS  40
#define MAX_NODES 100000

// Scratch (allocation-free: __device__ globals)
__device__ float g_support1[MAX_NODES * N_HID];  // X @ W1
__device__ float g_agg1[MAX_NODES * N_HID];      // segment_sum conv1
__device__ float g_agg2[MAX_NODES * N_HID];      // segment_sum conv2 (16-dim)

#define FMA_F32X2(d, a, b, c) \
    asm("fma.rn.f32x2 %0, %1, %2, %3;" : "=l"(d) : "l"(a), "l"(b), "l"(c))

#define CP_ASYNC16(dst, src, srcsz) \
    asm volatile("cp.async.cg.shared.global [%0], [%1], 16, %2;" \
                 :: "r"(dst), "l"(src), "r"(srcsz))
#define CP_COMMIT() asm volatile("cp.async.commit_group;" ::: "memory")
#define CP_WAIT1()  asm volatile("cp.async.wait_group 1;" ::: "memory")
#define CP_WAIT0()  asm volatile("cp.async.wait_group 0;" ::: "memory")

__device__ __forceinline__ uint32_t smem_u32(const void* p) {
    uint32_t a;
    asm("{ .reg .u64 tmp; cvta.to.shared.u64 tmp, %1; cvt.u32.u64 %0, tmp; }"
        : "=r"(a) : "l"(p));
    return a;
}

// ---------------------------------------------------------------------------
// Kernel 0: zero both aggregation buffers
// ---------------------------------------------------------------------------
__global__ void zero_kernel(int n_float4) {
    int i = blockIdx.x * blockDim.x + threadIdx.x;
    if (i >= n_float4) return;
    float4 z = make_float4(0.f, 0.f, 0.f, 0.f);
    reinterpret_cast<float4*>(g_agg1)[i] = z;
    reinterpret_cast<float4*>(g_agg2)[i] = z;
}

// ---------------------------------------------------------------------------
// Kernel 1: support1 = X @ W1   [nNodes,512] @ [512,16]
// R15 layout, but x is read from smem via 4x LDS.128 per row per chunk
// (conflict-free full-bank sweep) instead of 32 scalar LDS with 4-way
// conflicts. Crossbar drops below the FMA floor.
// ---------------------------------------------------------------------------
#define GKC    16
#define GROWS  256
#define GSTR   20            // 80 B row stride, 16B-aligned
#define NCHUNK (N_FEAT / GKC)   // 32
#define TILE_F (GROWS * GSTR)   // 5120 floats per buffer
#define WC_F   (GKC * N_HID)    // 256 floats per W buffer

__global__ __launch_bounds__(128) void gemm1_kernel(
    const float* __restrict__ X, const float* __restrict__ W1, int nNodes)
{
    __shared__ __align__(16) float tile[2][TILE_F];   // 2 x 20480 B
    __shared__ __align__(16) float sWc[2][WC_F];      // 2 x 1024 B

    int t = threadIdx.x;
    int rowbase = blockIdx.x * GROWS;

    uint32_t tile_b = smem_u32(&tile[0][0]);
    uint32_t wc_b   = smem_u32(&sWc[0][0]);

    // staging coords: 8 x 16-byte copies per thread per chunk
    const float* srcp[8];
    uint32_t     doff[8];
    int          ssz[8];
    #pragma unroll
    for (int j = 0; j < 8; j++) {
        int idx = t + 128 * j;
        int row = idx >> 2;
        int c16 = idx & 3;
        int grow = rowbase + row;
        bool ok = (grow < nNodes);
        srcp[j] = X + (size_t)(ok ? grow : 0) * N_FEAT + c16 * 4;
        doff[j] = (uint32_t)(row * GSTR + c16 * 4) * 4u;
        ssz[j]  = ok ? 16 : 0;
    }

    unsigned long long accA[8], accB[8];
    #pragma unroll
    for (int p = 0; p < 8; p++) { accA[p] = 0ULL; accB[p] = 0ULL; }

    // issue chunk `c` into buffer c&1
    auto issue = [&](int c) {
        int kc = c * GKC;
        int buf = c & 1;
        uint32_t tb = tile_b + buf * (TILE_F * 4);
        #pragma unroll
        for (int j = 0; j < 8; j++)
            CP_ASYNC16(tb + doff[j], srcp[j] + kc, ssz[j]);
        if (t < 64)
            CP_ASYNC16(wc_b + buf * (WC_F * 4) + t * 16,
                       W1 + kc * N_HID + t * 4, 16);
        CP_COMMIT();
    };

    issue(0);

    for (int c = 0; c < NCHUNK; c++) {
        int buf = c & 1;
        if (c < NCHUNK - 1) {
            issue(c + 1);
            CP_WAIT1();          // chunk c landed; c+1 in flight
        } else {
            CP_WAIT0();
        }
        __syncthreads();

        const float* tA = &tile[buf][t * GSTR];
        const float* tB = &tile[buf][(t + 128) * GSTR];
        const float* wc = &sWc[buf][0];

        // x rows via LDS.128 (conflict-free bank sweep), into registers
        float4 a4[4], b4[4];
        #pragma unroll
        for (int q = 0; q < 4; q++) {
            a4[q] = reinterpret_cast<const float4*>(tA)[q];
            b4[q] = reinterpret_cast<const float4*>(tB)[q];
        }

        #pragma unroll
        for (int q = 0; q < 4; q++) {
            #pragma unroll
            for (int s = 0; s < 4; s++) {
                int kk = q * 4 + s;
                float xa = (s == 0) ? a4[q].x : (s == 1) ? a4[q].y
                         : (s == 2) ? a4[q].z : a4[q].w;
                float xb = (s == 0) ? b4[q].x : (s == 1) ? b4[q].y
                         : (s == 2) ? b4[q].z : b4[q].w;
                unsigned long long xxa, xxb;
                asm("mov.b64 %0, {%1, %1};" : "=l"(xxa) : "f"(xa));
                asm("mov.b64 %0, {%1, %1};" : "=l"(xxb) : "f"(xb));

                const ulonglong2* wr =
                    reinterpret_cast<const ulonglong2*>(wc + kk * N_HID);
                ulonglong2 w0 = wr[0];   // broadcast LDS.128
                ulonglong2 w1 = wr[1];
                ulonglong2 w2 = wr[2];
                ulonglong2 w3 = wr[3];

                FMA_F32X2(accA[0], xxa, w0.x, accA[0]);
                FMA_F32X2(accA[1], xxa, w0.y, accA[1]);
                FMA_F32X2(accA[2], xxa, w1.x, accA[2]);
                FMA_F32X2(accA[3], xxa, w1.y, accA[3]);
                FMA_F32X2(accA[4], xxa, w2.x, accA[4]);
                FMA_F32X2(accA[5], xxa, w2.y, accA[5]);
                FMA_F32X2(accA[6], xxa, w3.x, accA[6]);
                FMA_F32X2(accA[7], xxa, w3.y, accA[7]);

                FMA_F32X2(accB[0], xxb, w0.x, accB[0]);
                FMA_F32X2(accB[1], xxb, w0.y, accB[1]);
                FMA_F32X2(accB[2], xxb, w1.x, accB[2]);
                FMA_F32X2(accB[3], xxb, w1.y, accB[3]);
                FMA_F32X2(accB[4], xxb, w2.x, accB[4]);
                FMA_F32X2(accB[5], xxb, w2.y, accB[5]);
                FMA_F32X2(accB[6], xxb, w3.x, accB[6]);
                FMA_F32X2(accB[7], xxb, w3.y, accB[7]);
            }
        }
        __syncthreads();
    }

    int r0 = rowbase + t;
    int r1 = rowbase + t + 128;
    if (r0 < nNodes) {
        float* o = g_support1 + (size_t)r0 * N_HID;
        #pragma unroll
        for (int q = 0; q < 4; q++) {
            ulonglong2 st; st.x = accA[q * 2]; st.y = accA[q * 2 + 1];
            *reinterpret_cast<ulonglong2*>(o + q * 4) = st;
        }
    }
    if (r1 < nNodes) {
        float* o = g_support1 + (size_t)r1 * N_HID;
        #pragma unroll
        for (int q = 0; q < 4; q++) {
            ulonglong2 st; st.x = accB[q * 2]; st.y = accB[q * 2 + 1];
            *reinterpret_cast<ulonglong2*>(o + q * 4) = st;
        }
    }
}

// ---------------------------------------------------------------------------
// Kernel 2a: conv1 aggregation (4 lanes/edge, red.global.add.v4)
// ---------------------------------------------------------------------------
__global__ __launch_bounds__(256) void aggregate1_kernel(
    const int* __restrict__ src, const int* __restrict__ dst,
    const float* __restrict__ ew, int nEdges)
{
    int gid = blockIdx.x * blockDim.x + threadIdx.x;
    int e = gid >> 2;
    if (e >= nEdges) return;
    int c = (gid & 3) << 2;

    int s = __ldg(src + e);
    int d = __ldg(dst + e);
    float w = __ldg(ew + e);

    float4 v = *reinterpret_cast<const float4*>(g_support1 + (size_t)s * N_HID + c);
    float* o = g_agg1 + (size_t)d * N_HID + c;
    asm volatile("red.global.add.v4.f32 [%0], {%1, %2, %3, %4};"
                 :: "l"(o), "f"(v.x * w), "f"(v.y * w), "f"(v.z * w), "f"(v.w * w)
                 : "memory");
}

// ---------------------------------------------------------------------------
// Kernel 2b: conv2 aggregation, fused bias+relu on the gathered value:
//   agg2[d] += w * relu(agg1[s] + b1)
// ---------------------------------------------------------------------------
__global__ __launch_bounds__(256) void aggregate2_kernel(
    const int* __restrict__ src, const int* __restrict__ dst,
    const float* __restrict__ ew, const float* __restrict__ b1, int nEdges)
{
    int gid = blockIdx.x * blockDim.x + threadIdx.x;
    int e = gid >> 2;
    if (e >= nEdges) return;
    int c = (gid & 3) << 2;

    int s = __ldg(src + e);
    int d = __ldg(dst + e);
    float w = __ldg(ew + e);

    float4 v = *reinterpret_cast<const float4*>(g_agg1 + (size_t)s * N_HID + c);
    float4 b = *reinterpret_cast<const float4*>(b1 + c);
    v.x = fmaxf(v.x + b.x, 0.f) * w;
    v.y = fmaxf(v.y + b.y, 0.f) * w;
    v.z = fmaxf(v.z + b.z, 0.f) * w;
    v.w = fmaxf(v.w + b.w, 0.f) * w;

    float* o = g_agg2 + (size_t)d * N_HID + c;
    asm volatile("red.global.add.v4.f32 [%0], {%1, %2, %3, %4};"
                 :: "l"(o), "f"(v.x), "f"(v.y), "f"(v.z), "f"(v.w)
                 : "memory");
}

// ---------------------------------------------------------------------------
// Kernel 3: out = log_softmax(agg2 @ W2 + b2)
// ---------------------------------------------------------------------------
__global__ __launch_bounds__(128) void head_kernel(
    const float* __restrict__ W2, const float* __restrict__ b2,
    float* __restrict__ out, int nNodes)
{
    __shared__ float sW[N_HID * N_CLS];
    __shared__ float sb[N_CLS];
    for (int i = threadIdx.x; i < N_HID * N_CLS; i += blockDim.x) sW[i] = W2[i];
    for (int i = threadIdx.x; i < N_CLS; i += blockDim.x) sb[i] = b2[i];
    __syncthreads();

    int node = blockIdx.x * blockDim.x + threadIdx.x;
    if (node >= nNodes) return;

    float v[N_HID];
    const float4* vp = reinterpret_cast<const float4*>(g_agg2 + (size_t)node * N_HID);
    #pragma unroll
    for (int q = 0; q < 4; q++) {
        float4 tt = vp[q];
        v[q * 4 + 0] = tt.x; v[q * 4 + 1] = tt.y; v[q * 4 + 2] = tt.z; v[q * 4 + 3] = tt.w;
    }

    float y[N_CLS];
    #pragma unroll
    for (int c = 0; c < N_CLS; c++) y[c] = sb[c];
    #pragma unroll
    for (int k = 0; k < N_HID; k++) {
        float vk = v[k];
        const float* wr = sW + k * N_CLS;
        #pragma unroll
        for (int c = 0; c < N_CLS; c++)
            y[c] = fmaf(vk, wr[c], y[c]);
    }

    float mx = y[0];
    #pragma unroll
    for (int c = 1; c < N_CLS; c++) mx = fmaxf(mx, y[c]);
    float sum = 0.f;
    #pragma unroll
    for (int c = 0; c < N_CLS; c++) sum += __expf(y[c] - mx);
    float lse = mx + __logf(sum);

    float* o = out + (size_t)node * N_CLS;
    #pragma unroll
    for (int q = 0; q < N_CLS / 4; q++) {
        float4 st = make_float4(y[q * 4 + 0] - lse, y[q * 4 + 1] - lse,
                                y[q * 4 + 2] - lse, y[q * 4 + 3] - lse);
        *reinterpret_cast<float4*>(o + q * 4) = st;
    }
}

// ---------------------------------------------------------------------------
// Launcher — zero forked onto a side stream, overlapping gemm1.
// ---------------------------------------------------------------------------
extern "C" void kernel_launch(void* const* d_in, const int* in_sizes, int n_in,
                              void* d_out, int out_size)
{
    const float* x        = (const float*)d_in[0];
    const int*   edge_src = (const int*)  d_in[1];
    const int*   edge_dst = (const int*)  d_in[2];
    const float* edge_w   = (const float*)d_in[3];
    const float* W1       = (const float*)d_in[4];
    const float* b1       = (const float*)d_in[5];
    const float* W2       = (const float*)d_in[6];
    const float* b2       = (const float*)d_in[7];
    float* out = (float*)d_out;

    int nNodes = in_sizes[0] / N_FEAT;
    int nEdges = in_sizes[1];
    int n_f4 = nNodes * N_HID / 4;

    cudaStream_t s2 = 0;
    cudaEvent_t evF = 0, evJ = 0;
    bool forked =
        (cudaStreamCreateWithFlags(&s2, cudaStreamNonBlocking) == cudaSuccess) &&
        (cudaEventCreateWithFlags(&evF, cudaEventDisableTiming) == cudaSuccess) &&
        (cudaEventCreateWithFlags(&evJ, cudaEventDisableTiming) == cudaSuccess);
    if (!forked) s2 = 0;

    if (forked) {
        cudaEventRecord(evF, 0);
        cudaStreamWaitEvent(s2, evF, 0);
    }

    zero_kernel<<<(n_f4 + 255) / 256, 256, 0, s2>>>(n_f4);

    gemm1_kernel<<<(nNodes + GROWS - 1) / GROWS, 128>>>(x, W1, nNodes);

    if (forked) {
        cudaEventRecord(evJ, s2);
        cudaStreamWaitEvent(0, evJ, 0);
    }

    int aggThreads = nEdges * 4;
    aggregate1_kernel<<<(aggThreads + 255) / 256, 256>>>(
        edge_src, edge_dst, edge_w, nEdges);

    aggregate2_kernel<<<(aggThreads + 255) / 256, 256>>>(
        edge_src, edge_dst, edge_w, b1, nEdges);

    head_kernel<<<(nNodes + 127) / 128, 128>>>(W2, b2, out, nNodes);
}

// round 17
// speedup vs baseline: 1.0192x; 1.0192x over previous
#include <cuda_runtime.h>
#include <cstdint>

#define N_FEAT 512
#define N_HID  16
#define N_CLS  40
#define MAX_NODES 100000

// Scratch (allocation-free: __device__ globals)
__device__ float g_support1[MAX_NODES * N_HID];  // X @ W1
__device__ float g_agg1[MAX_NODES * N_HID];      // segment_sum conv1
__device__ float g_agg2[MAX_NODES * N_HID];      // segment_sum conv2 (16-dim)

#define FMA_F32X2(d, a, b, c) \
    asm("fma.rn.f32x2 %0, %1, %2, %3;" : "=l"(d) : "l"(a), "l"(b), "l"(c))

#define CP_ASYNC16(dst, src, srcsz) \
    asm volatile("cp.async.cg.shared.global [%0], [%1], 16, %2;" \
                 :: "r"(dst), "l"(src), "r"(srcsz))
#define CP_COMMIT() asm volatile("cp.async.commit_group;" ::: "memory")
#define CP_WAIT1()  asm volatile("cp.async.wait_group 1;" ::: "memory")
#define CP_WAIT0()  asm volatile("cp.async.wait_group 0;" ::: "memory")

__device__ __forceinline__ uint32_t smem_u32(const void* p) {
    uint32_t a;
    asm("{ .reg .u64 tmp; cvta.to.shared.u64 tmp, %1; cvt.u32.u64 %0, tmp; }"
        : "=r"(a) : "l"(p));
    return a;
}

// ---------------------------------------------------------------------------
// Kernel 0: zero both aggregation buffers
// ---------------------------------------------------------------------------
__global__ void zero_kernel(int n_float4) {
    int i = blockIdx.x * blockDim.x + threadIdx.x;
    if (i >= n_float4) return;
    float4 z = make_float4(0.f, 0.f, 0.f, 0.f);
    reinterpret_cast<float4*>(g_agg1)[i] = z;
    reinterpret_cast<float4*>(g_agg2)[i] = z;
}

// ---------------------------------------------------------------------------
// Kernel 1: support1 = X @ W1   [nNodes,512] @ [512,16]  (R15's proven config)
// 128 thr/block, 2 rows/thr, GKC=16, NBUF=2, 16B cp.async.cg staging.
// ---------------------------------------------------------------------------
#define GKC    16
#define GROWS  256
#define GSTR   20            // 80 B row stride, 16B-aligned
#define NCHUNK (N_FEAT / GKC)   // 32
#define TILE_F (GROWS * GSTR)   // 5120 floats per buffer
#define WC_F   (GKC * N_HID)    // 256 floats per W buffer

__global__ __launch_bounds__(128) void gemm1_kernel(
    const float* __restrict__ X, const float* __restrict__ W1, int nNodes)
{
    __shared__ __align__(16) float tile[2][TILE_F];   // 2 x 20480 B
    __shared__ __align__(16) float sWc[2][WC_F];      // 2 x 1024 B

    int t = threadIdx.x;
    int rowbase = blockIdx.x * GROWS;

    uint32_t tile_b = smem_u32(&tile[0][0]);
    uint32_t wc_b   = smem_u32(&sWc[0][0]);

    const float* srcp[8];
    uint32_t     doff[8];
    int          ssz[8];
    #pragma unroll
    for (int j = 0; j < 8; j++) {
        int idx = t + 128 * j;
        int row = idx >> 2;
        int c16 = idx & 3;
        int grow = rowbase + row;
        bool ok = (grow < nNodes);
        srcp[j] = X + (size_t)(ok ? grow : 0) * N_FEAT + c16 * 4;
        doff[j] = (uint32_t)(row * GSTR + c16 * 4) * 4u;
        ssz[j]  = ok ? 16 : 0;
    }

    unsigned long long accA[8], accB[8];
    #pragma unroll
    for (int p = 0; p < 8; p++) { accA[p] = 0ULL; accB[p] = 0ULL; }

    auto issue = [&](int c) {
        int kc = c * GKC;
        int buf = c & 1;
        uint32_t tb = tile_b + buf * (TILE_F * 4);
        #pragma unroll
        for (int j = 0; j < 8; j++)
            CP_ASYNC16(tb + doff[j], srcp[j] + kc, ssz[j]);
        if (t < 64)
            CP_ASYNC16(wc_b + buf * (WC_F * 4) + t * 16,
                       W1 + kc * N_HID + t * 4, 16);
        CP_COMMIT();
    };

    issue(0);

    for (int c = 0; c < NCHUNK; c++) {
        int buf = c & 1;
        if (c < NCHUNK - 1) {
            issue(c + 1);
            CP_WAIT1();
        } else {
            CP_WAIT0();
        }
        __syncthreads();

        const float* tA = &tile[buf][t * GSTR];
        const float* tB = &tile[buf][(t + 128) * GSTR];
        const float* wc = &sWc[buf][0];

        #pragma unroll
        for (int kk = 0; kk < GKC; kk++) {
            float xa = tA[kk];
            float xb = tB[kk];
            unsigned long long xxa, xxb;
            asm("mov.b64 %0, {%1, %1};" : "=l"(xxa) : "f"(xa));
            asm("mov.b64 %0, {%1, %1};" : "=l"(xxb) : "f"(xb));

            const ulonglong2* wr =
                reinterpret_cast<const ulonglong2*>(wc + kk * N_HID);
            ulonglong2 w0 = wr[0];
            ulonglong2 w1 = wr[1];
            ulonglong2 w2 = wr[2];
            ulonglong2 w3 = wr[3];

            FMA_F32X2(accA[0], xxa, w0.x, accA[0]);
            FMA_F32X2(accA[1], xxa, w0.y, accA[1]);
            FMA_F32X2(accA[2], xxa, w1.x, accA[2]);
            FMA_F32X2(accA[3], xxa, w1.y, accA[3]);
            FMA_F32X2(accA[4], xxa, w2.x, accA[4]);
            FMA_F32X2(accA[5], xxa, w2.y, accA[5]);
            FMA_F32X2(accA[6], xxa, w3.x, accA[6]);
            FMA_F32X2(accA[7], xxa, w3.y, accA[7]);

            FMA_F32X2(accB[0], xxb, w0.x, accB[0]);
            FMA_F32X2(accB[1], xxb, w0.y, accB[1]);
            FMA_F32X2(accB[2], xxb, w1.x, accB[2]);
            FMA_F32X2(accB[3], xxb, w1.y, accB[3]);
            FMA_F32X2(accB[4], xxb, w2.x, accB[4]);
            FMA_F32X2(accB[5], xxb, w2.y, accB[5]);
            FMA_F32X2(accB[6], xxb, w3.x, accB[6]);
            FMA_F32X2(accB[7], xxb, w3.y, accB[7]);
        }
        __syncthreads();
    }

    int r0 = rowbase + t;
    int r1 = rowbase + t + 128;
    if (r0 < nNodes) {
        float* o = g_support1 + (size_t)r0 * N_HID;
        #pragma unroll
        for (int q = 0; q < 4; q++) {
            ulonglong2 st; st.x = accA[q * 2]; st.y = accA[q * 2 + 1];
            *reinterpret_cast<ulonglong2*>(o + q * 4) = st;
        }
    }
    if (r1 < nNodes) {
        float* o = g_support1 + (size_t)r1 * N_HID;
        #pragma unroll
        for (int q = 0; q < 4; q++) {
            ulonglong2 st; st.x = accB[q * 2]; st.y = accB[q * 2 + 1];
            *reinterpret_cast<ulonglong2*>(o + q * 4) = st;
        }
    }
}

// ---------------------------------------------------------------------------
// Kernel 2a: conv1 aggregation. PDL: index loads (independent of gemm1 output)
// run in the prologue; griddepsync before touching g_support1.
// ---------------------------------------------------------------------------
__global__ __launch_bounds__(256) void aggregate1_kernel(
    const int* __restrict__ src, const int* __restrict__ dst,
    const float* __restrict__ ew, int nEdges)
{
    int gid = blockIdx.x * blockDim.x + threadIdx.x;
    int e = gid >> 2;
    if (e >= nEdges) return;
    int c = (gid & 3) << 2;

    // prologue: independent of predecessor's output
    int s = __ldg(src + e);
    int d = __ldg(dst + e);
    float w = __ldg(ew + e);

#if __CUDA_ARCH__ >= 900
    cudaGridDependencySynchronize();   // wait for gemm1's writes
#endif

    float4 v = *reinterpret_cast<const float4*>(g_support1 + (size_t)s * N_HID + c);
    float* o = g_agg1 + (size_t)d * N_HID + c;
    asm volatile("red.global.add.v4.f32 [%0], {%1, %2, %3, %4};"
                 :: "l"(o), "f"(v.x * w), "f"(v.y * w), "f"(v.z * w), "f"(v.w * w)
                 : "memory");
}

// ---------------------------------------------------------------------------
// Kernel 2b: conv2 aggregation, fused bias+relu. PDL prologue likewise.
// ---------------------------------------------------------------------------
__global__ __launch_bounds__(256) void aggregate2_kernel(
    const int* __restrict__ src, const int* __restrict__ dst,
    const float* __restrict__ ew, const float* __restrict__ b1, int nEdges)
{
    int gid = blockIdx.x * blockDim.x + threadIdx.x;
    int e = gid >> 2;
    if (e >= nEdges) return;
    int c = (gid & 3) << 2;

    int s = __ldg(src + e);
    int d = __ldg(dst + e);
    float w = __ldg(ew + e);
    float4 b = *reinterpret_cast<const float4*>(b1 + c);  // input, independent

#if __CUDA_ARCH__ >= 900
    cudaGridDependencySynchronize();   // wait for agg1's REDs
#endif

    float4 v = *reinterpret_cast<const float4*>(g_agg1 + (size_t)s * N_HID + c);
    v.x = fmaxf(v.x + b.x, 0.f) * w;
    v.y = fmaxf(v.y + b.y, 0.f) * w;
    v.z = fmaxf(v.z + b.z, 0.f) * w;
    v.w = fmaxf(v.w + b.w, 0.f) * w;

    float* o = g_agg2 + (size_t)d * N_HID + c;
    asm volatile("red.global.add.v4.f32 [%0], {%1, %2, %3, %4};"
                 :: "l"(o), "f"(v.x), "f"(v.y), "f"(v.z), "f"(v.w)
                 : "memory");
}

// ---------------------------------------------------------------------------
// Kernel 3: out = log_softmax(agg2 @ W2 + b2). PDL: stage weights first.
// ---------------------------------------------------------------------------
__global__ __launch_bounds__(128) void head_kernel(
    const float* __restrict__ W2, const float* __restrict__ b2,
    float* __restrict__ out, int nNodes)
{
    __shared__ float sW[N_HID * N_CLS];
    __shared__ float sb[N_CLS];
    for (int i = threadIdx.x; i < N_HID * N_CLS; i += blockDim.x) sW[i] = W2[i];
    for (int i = threadIdx.x; i < N_CLS; i += blockDim.x) sb[i] = b2[i];
    __syncthreads();

#if __CUDA_ARCH__ >= 900
    cudaGridDependencySynchronize();   // wait for agg2's REDs
#endif

    int node = blockIdx.x * blockDim.x + threadIdx.x;
    if (node >= nNodes) return;

    float v[N_HID];
    const float4* vp = reinterpret_cast<const float4*>(g_agg2 + (size_t)node * N_HID);
    #pragma unroll
    for (int q = 0; q < 4; q++) {
        float4 tt = vp[q];
        v[q * 4 + 0] = tt.x; v[q * 4 + 1] = tt.y; v[q * 4 + 2] = tt.z; v[q * 4 + 3] = tt.w;
    }

    float y[N_CLS];
    #pragma unroll
    for (int c = 0; c < N_CLS; c++) y[c] = sb[c];
    #pragma unroll
    for (int k = 0; k < N_HID; k++) {
        float vk = v[k];
        const float* wr = sW + k * N_CLS;
        #pragma unroll
        for (int c = 0; c < N_CLS; c++)
            y[c] = fmaf(vk, wr[c], y[c]);
    }

    float mx = y[0];
    #pragma unroll
    for (int c = 1; c < N_CLS; c++) mx = fmaxf(mx, y[c]);
    float sum = 0.f;
    #pragma unroll
    for (int c = 0; c < N_CLS; c++) sum += __expf(y[c] - mx);
    float lse = mx + __logf(sum);

    float* o = out + (size_t)node * N_CLS;
    #pragma unroll
    for (int q = 0; q < N_CLS / 4; q++) {
        float4 st = make_float4(y[q * 4 + 0] - lse, y[q * 4 + 1] - lse,
                                y[q * 4 + 2] - lse, y[q * 4 + 3] - lse);
        *reinterpret_cast<float4*>(o + q * 4) = st;
    }
}

// ---------------------------------------------------------------------------
// Launcher — zero forked to side stream; agg1/agg2/head launched with
// programmatic stream serialization (PDL). Fallback to normal launches if
// the Ex-launch fails (griddepsync is then an immediate no-op: still correct).
// ---------------------------------------------------------------------------
extern "C" void kernel_launch(void* const* d_in, const int* in_sizes, int n_in,
                              void* d_out, int out_size)
{
    const float* x        = (const float*)d_in[0];
    const int*   edge_src = (const int*)  d_in[1];
    const int*   edge_dst = (const int*)  d_in[2];
    const float* edge_w   = (const float*)d_in[3];
    const float* W1       = (const float*)d_in[4];
    const float* b1       = (const float*)d_in[5];
    const float* W2       = (const float*)d_in[6];
    const float* b2       = (const float*)d_in[7];
    float* out = (float*)d_out;

    int nNodes = in_sizes[0] / N_FEAT;
    int nEdges = in_sizes[1];
    int n_f4 = nNodes * N_HID / 4;

    cudaStream_t s2 = 0;
    cudaEvent_t evF = 0, evJ = 0;
    bool forked =
        (cudaStreamCreateWithFlags(&s2, cudaStreamNonBlocking) == cudaSuccess) &&
        (cudaEventCreateWithFlags(&evF, cudaEventDisableTiming) == cudaSuccess) &&
        (cudaEventCreateWithFlags(&evJ, cudaEventDisableTiming) == cudaSuccess);
    if (!forked) s2 = 0;

    if (forked) {
        cudaEventRecord(evF, 0);
        cudaStreamWaitEvent(s2, evF, 0);
    }

    zero_kernel<<<(n_f4 + 255) / 256, 256, 0, s2>>>(n_f4);

    gemm1_kernel<<<(nNodes + GROWS - 1) / GROWS, 128>>>(x, W1, nNodes);

    if (forked) {
        cudaEventRecord(evJ, s2);
        cudaStreamWaitEvent(0, evJ, 0);
    }

    // PDL launch config (default stream)
    cudaLaunchAttribute pdlAttr[1];
    pdlAttr[0].id = cudaLaunchAttributeProgrammaticStreamSerialization;
    pdlAttr[0].val.programmaticStreamSerializationAllowed = 1;

    int aggThreads = nEdges * 4;
    unsigned aggBlocks = (unsigned)((aggThreads + 255) / 256);
    unsigned headBlocks = (unsigned)((nNodes + 127) / 128);

    {   // agg1
        cudaLaunchConfig_t cfg = {};
        cfg.gridDim = {aggBlocks, 1, 1};
        cfg.blockDim = {256, 1, 1};
        cfg.attrs = pdlAttr;
        cfg.numAttrs = 1;
        if (cudaLaunchKernelEx(&cfg, aggregate1_kernel,
                               edge_src, edge_dst, edge_w, nEdges) != cudaSuccess)
            aggregate1_kernel<<<aggBlocks, 256>>>(edge_src, edge_dst, edge_w, nEdges);
    }
    {   // agg2
        cudaLaunchConfig_t cfg = {};
        cfg.gridDim = {aggBlocks, 1, 1};
        cfg.blockDim = {256, 1, 1};
        cfg.attrs = pdlAttr;
        cfg.numAttrs = 1;
        if (cudaLaunchKernelEx(&cfg, aggregate2_kernel,
                               edge_src, edge_dst, edge_w, b1, nEdges) != cudaSuccess)
            aggregate2_kernel<<<aggBlocks, 256>>>(edge_src, edge_dst, edge_w, b1, nEdges);
    }
    {   // head
        cudaLaunchConfig_t cfg = {};
        cfg.gridDim = {headBlocks, 1, 1};
        cfg.blockDim = {128, 1, 1};
        cfg.attrs = pdlAttr;
        cfg.numAttrs = 1;
        if (cudaLaunchKernelEx(&cfg, head_kernel,
                               W2, b2, out, nNodes) != cudaSuccess)
            head_kernel<<<headBlocks, 128>>>(W2, b2, out, nNodes);
    }
}